// round 2
// baseline (speedup 1.0000x reference)
#include <cuda_runtime.h>

#define N_NODES   100000
#define N_EDGES   1600000
#define N_TOT     1700000   // edges + self loops
#define N_GRAPHSX 2048
#define H         100
#define H4        25        // H / 4 (float4 groups)
#define BN_EPS    1e-5f
#define NBLK_SCAN 98        // ceil(100000/1024)

// ---------------- scratch (static device globals; no allocs) ----------------
__device__ __align__(16) float g_bufA[N_NODES * H];   // h (layer input / agg output)
__device__ __align__(16) float g_bufB[N_NODES * H];   // y = dis * (h @ W)
__device__ __align__(16) float g_pool[N_GRAPHSX * H];
__device__ __align__(16) float g_bnS[4 * H];
__device__ __align__(16) float g_bnT[4 * H];
__device__ float g_dis[N_NODES];
__device__ int   g_colptr[N_NODES + 1];
__device__ int   g_cursor[N_NODES];
__device__ int   g_csrsrc[N_TOT];
__device__ int   g_src[N_EDGES];
__device__ int   g_dst[N_EDGES];
__device__ int   g_batch[N_NODES];
__device__ int   g_bsum[128];
__device__ int   g_boff[128];
__device__ int   g_is64;

// ---------------- dtype probe + conversion ----------------
// int64 (little-endian, values < 2^31): every odd 32-bit word is 0.
// int32 (uniform [0,100000)): odd words ~never all zero over 64 samples.
__global__ void k_probe(const unsigned* __restrict__ ebuf) {
    if (threadIdx.x == 0) {
        int all0 = 1;
        for (int i = 1; i < 128; i += 2) all0 &= (ebuf[i] == 0u);
        g_is64 = all0;
    }
}

__global__ void k_cvt_edges(const void* __restrict__ ebuf) {
    int e = blockIdx.x * blockDim.x + threadIdx.x;
    if (e >= N_EDGES) return;
    if (g_is64) {
        const long long* p = (const long long*)ebuf;
        g_src[e] = (int)p[e];
        g_dst[e] = (int)p[N_EDGES + e];
    } else {
        const int* p = (const int*)ebuf;
        g_src[e] = p[e];
        g_dst[e] = p[N_EDGES + e];
    }
}

__global__ void k_cvt_batch(const void* __restrict__ bbuf) {
    int i = blockIdx.x * blockDim.x + threadIdx.x;
    if (i >= N_NODES) return;
    g_batch[i] = g_is64 ? (int)((const long long*)bbuf)[i] : ((const int*)bbuf)[i];
}

// ---------------- CSR build ----------------
__global__ void k_init() {
    int i = blockIdx.x * blockDim.x + threadIdx.x;
    if (i < N_NODES) g_cursor[i] = 1;           // self loop counted
    if (i < N_GRAPHSX * H) g_pool[i] = 0.f;
}

__global__ void k_count() {
    int e = blockIdx.x * blockDim.x + threadIdx.x;
    if (e < N_EDGES) atomicAdd(&g_cursor[g_dst[e]], 1);
}

__global__ void k_scan_a() {
    __shared__ int red[256];
    int b = blockIdx.x, t = threadIdx.x;
    int base = b * 1024 + t * 4;
    int s = 0;
#pragma unroll
    for (int j = 0; j < 4; j++) {
        int idx = base + j;
        if (idx < N_NODES) {
            int c = g_cursor[idx];
            s += c;
            g_dis[idx] = rsqrtf((float)c);      // deg >= 1 always (self loop)
        }
    }
    red[t] = s; __syncthreads();
    for (int off = 128; off > 0; off >>= 1) {
        if (t < off) red[t] += red[t + off];
        __syncthreads();
    }
    if (t == 0) g_bsum[b] = red[0];
}

__global__ void k_scan_b() {
    if (threadIdx.x == 0) {
        int acc = 0;
        for (int i = 0; i < NBLK_SCAN; i++) { g_boff[i] = acc; acc += g_bsum[i]; }
        g_colptr[N_NODES] = acc;
    }
}

__global__ void k_scan_c() {
    __shared__ int wsum[8], woff[8];
    int b = blockIdx.x, t = threadIdx.x;
    int base = b * 1024 + t * 4;
    int v[4];
#pragma unroll
    for (int j = 0; j < 4; j++) {
        int idx = base + j;
        v[j] = (idx < N_NODES) ? g_cursor[idx] : 0;
    }
    int s = v[0] + v[1] + v[2] + v[3];
    int lane = t & 31, w = t >> 5;
    int x = s;
#pragma unroll
    for (int off = 1; off < 32; off <<= 1) {
        int y = __shfl_up_sync(0xffffffffu, x, off);
        if (lane >= off) x += y;
    }
    if (lane == 31) wsum[w] = x;
    __syncthreads();
    if (t == 0) { int a = 0; for (int i = 0; i < 8; i++) { woff[i] = a; a += wsum[i]; } }
    __syncthreads();
    int excl = (x - s) + woff[w] + g_boff[b];
#pragma unroll
    for (int j = 0; j < 4; j++) {
        int idx = base + j;
        if (idx < N_NODES) g_colptr[idx] = excl;
        excl += v[j];
    }
}

__global__ void k_fillself() {
    int n = blockIdx.x * blockDim.x + threadIdx.x;
    if (n < N_NODES) {
        int p = g_colptr[n];
        g_csrsrc[p] = n;            // self loop edge
        g_cursor[n] = p + 1;
    }
}

__global__ void k_filledges() {
    int e = blockIdx.x * blockDim.x + threadIdx.x;
    if (e < N_EDGES) {
        int p = atomicAdd(&g_cursor[g_dst[e]], 1);
        g_csrsrc[p] = g_src[e];
    }
}

__global__ void k_bnprep(const float* __restrict__ bias, const float* __restrict__ gamma,
                         const float* __restrict__ beta, const float* __restrict__ mean,
                         const float* __restrict__ var) {
    int i = blockIdx.x * blockDim.x + threadIdx.x;
    if (i < 4 * H) {
        float s = gamma[i] * rsqrtf(var[i] + BN_EPS);
        g_bnS[i] = s;
        g_bnT[i] = (bias[i] - mean[i]) * s + beta[i];
    }
}

// ---------------- GEMM: y = dis[n] * (A @ W), A [N,K] -> g_bufB [N,100] ------
// BM=64, BN=128 (cols padded, store first 100), BK=32, 256 threads, 4x8/thread
__global__ void k_gemm(const float* __restrict__ Aext, int K, int use_ext,
                       const float* __restrict__ W) {
    const float* A = use_ext ? Aext : g_bufA;
    __shared__ float As[32][68];
    __shared__ float Wsm[32][128];
    int row0 = blockIdx.x * 64;
    int t = threadIdx.x;
    int ri = t >> 4, ci = t & 15;    // rows ri*4..+3, cols ci*8..+7
    float acc[4][8];
#pragma unroll
    for (int r = 0; r < 4; r++)
#pragma unroll
        for (int c = 0; c < 8; c++) acc[r][c] = 0.f;

    int ktiles = (K + 31) >> 5;
    for (int kt = 0; kt < ktiles; kt++) {
        int k0 = kt << 5;
#pragma unroll
        for (int i = t; i < 64 * 32; i += 256) {
            int r = i >> 5, k = i & 31;
            int gr = row0 + r, gk = k0 + k;
            As[k][r] = (gr < N_NODES && gk < K) ? A[gr * K + gk] : 0.f;
        }
#pragma unroll
        for (int i = t; i < 32 * 128; i += 256) {
            int k = i >> 7, c = i & 127;
            int gk = k0 + k;
            Wsm[k][c] = (gk < K && c < H) ? W[gk * H + c] : 0.f;
        }
        __syncthreads();
#pragma unroll 8
        for (int k = 0; k < 32; k++) {
            float4 a4 = *(const float4*)&As[k][ri * 4];
            float4 w0 = *(const float4*)&Wsm[k][ci * 8];
            float4 w1 = *(const float4*)&Wsm[k][ci * 8 + 4];
            float av[4] = {a4.x, a4.y, a4.z, a4.w};
            float wv[8] = {w0.x, w0.y, w0.z, w0.w, w1.x, w1.y, w1.z, w1.w};
#pragma unroll
            for (int r = 0; r < 4; r++)
#pragma unroll
                for (int c = 0; c < 8; c++)
                    acc[r][c] = fmaf(av[r], wv[c], acc[r][c]);
        }
        __syncthreads();
    }

    int c0 = ci * 8;
#pragma unroll
    for (int r = 0; r < 4; r++) {
        int gr = row0 + ri * 4 + r;
        if (gr >= N_NODES) break;
        float d = g_dis[gr];
        if (c0 < H) {
            float4 o = make_float4(acc[r][0] * d, acc[r][1] * d, acc[r][2] * d, acc[r][3] * d);
            *(float4*)&g_bufB[gr * H + c0] = o;
        }
        if (c0 + 4 < H) {
            float4 o = make_float4(acc[r][4] * d, acc[r][5] * d, acc[r][6] * d, acc[r][7] * d);
            *(float4*)&g_bufB[gr * H + c0 + 4] = o;
        }
    }
}

// ---------------- aggregation: h' = bn(dis[n] * sum_{src} y[src]) (+relu) ---
// warp per node, lanes 0..24 each own 4 channels (one float4)
__global__ void k_agg(int layer, int relu) {
    int gwarp = (blockIdx.x * blockDim.x + threadIdx.x) >> 5;
    int lane = threadIdx.x & 31;
    if (gwarp >= N_NODES) return;
    int n = gwarp;
    int beg = g_colptr[n], end = g_colptr[n + 1];
    if (lane < H4) {
        const float4* Y4 = (const float4*)g_bufB;
        float ax = 0.f, ay = 0.f, az = 0.f, aw = 0.f;
        float bx = 0.f, by = 0.f, bz = 0.f, bw = 0.f;
        int i = beg;
        for (; i + 1 < end; i += 2) {
            int s0 = g_csrsrc[i], s1 = g_csrsrc[i + 1];
            float4 f0 = Y4[s0 * H4 + lane];
            float4 f1 = Y4[s1 * H4 + lane];
            ax += f0.x; ay += f0.y; az += f0.z; aw += f0.w;
            bx += f1.x; by += f1.y; bz += f1.z; bw += f1.w;
        }
        if (i < end) {
            int s0 = g_csrsrc[i];
            float4 f0 = Y4[s0 * H4 + lane];
            ax += f0.x; ay += f0.y; az += f0.z; aw += f0.w;
        }
        ax += bx; ay += by; az += bz; aw += bw;
        float d = g_dis[n];
        int c = layer * H + lane * 4;
        float4 S = *(const float4*)&g_bnS[c];
        float4 T = *(const float4*)&g_bnT[c];
        float4 o;
        o.x = fmaf(ax * d, S.x, T.x);
        o.y = fmaf(ay * d, S.y, T.y);
        o.z = fmaf(az * d, S.z, T.z);
        o.w = fmaf(aw * d, S.w, T.w);
        if (relu) {
            o.x = fmaxf(o.x, 0.f); o.y = fmaxf(o.y, 0.f);
            o.z = fmaxf(o.z, 0.f); o.w = fmaxf(o.w, 0.f);
        }
        ((float4*)g_bufA)[n * H4 + lane] = o;
    }
}

// ---------------- pool + head ----------------
__global__ void k_pool() {
    int gwarp = (blockIdx.x * blockDim.x + threadIdx.x) >> 5;
    int lane = threadIdx.x & 31;
    if (gwarp >= N_NODES) return;
    if (lane < H4) {
        float4 v = ((const float4*)g_bufA)[gwarp * H4 + lane];
        int g = g_batch[gwarp];
        float* base = &g_pool[g * H + lane * 4];
        atomicAdd(base + 0, v.x);
        atomicAdd(base + 1, v.y);
        atomicAdd(base + 2, v.z);
        atomicAdd(base + 3, v.w);
    }
}

__global__ void k_head(const float* __restrict__ hW, const float* __restrict__ hb,
                       float* __restrict__ out) {
    int gwarp = (blockIdx.x * blockDim.x + threadIdx.x) >> 5;
    int lane = threadIdx.x & 31;
    if (gwarp >= N_GRAPHSX) return;
    float s = 0.f;
    if (lane < H4) {
        float4 g4 = ((const float4*)g_pool)[gwarp * H4 + lane];
        float4 w4 = ((const float4*)hW)[lane];
        s = g4.x * w4.x + g4.y * w4.y + g4.z * w4.z + g4.w * w4.w;
    }
#pragma unroll
    for (int off = 16; off > 0; off >>= 1)
        s += __shfl_down_sync(0xffffffffu, s, off);
    if (lane == 0) {
        float o = s + hb[0];
        out[gwarp] = (o >= 0.f) ? o : 0.1f * o;
    }
}

// ---------------- launch ----------------
extern "C" void kernel_launch(void* const* d_in, const int* in_sizes, int n_in,
                              void* d_out, int out_size) {
    const float* x      = (const float*)d_in[0];
    const void*  ei     = d_in[1];
    const void*  batch  = d_in[2];
    const float* W0     = (const float*)d_in[3];
    const float* Ws     = (const float*)d_in[4];
    const float* biases = (const float*)d_in[5];
    const float* gamma  = (const float*)d_in[6];
    const float* beta   = (const float*)d_in[7];
    const float* mean   = (const float*)d_in[8];
    const float* var    = (const float*)d_in[9];
    const float* headW  = (const float*)d_in[10];
    const float* headb  = (const float*)d_in[11];
    float* out = (float*)d_out;

    // dtype probe + conversion (int32 vs int64 edge/batch buffers)
    k_probe<<<1, 32>>>((const unsigned*)ei);
    k_cvt_edges<<<(N_EDGES + 255) / 256, 256>>>(ei);
    k_cvt_batch<<<(N_NODES + 255) / 256, 256>>>(batch);

    // CSR build (per replay; deterministic)
    k_init<<<800, 256>>>();
    k_count<<<(N_EDGES + 255) / 256, 256>>>();
    k_scan_a<<<NBLK_SCAN, 256>>>();
    k_scan_b<<<1, 32>>>();
    k_scan_c<<<NBLK_SCAN, 256>>>();
    k_fillself<<<(N_NODES + 255) / 256, 256>>>();
    k_filledges<<<(N_EDGES + 255) / 256, 256>>>();
    k_bnprep<<<2, 256>>>(biases, gamma, beta, mean, var);

    int gemm_blocks = (N_NODES + 63) / 64;
    int agg_blocks  = (N_NODES * 32 + 255) / 256;

    // layer 0: K=33, input = x
    k_gemm<<<gemm_blocks, 256>>>(x, 33, 1, W0);
    k_agg<<<agg_blocks, 256>>>(0, 1);
    // layers 1..3: K=100, input = g_bufA
    for (int l = 1; l < 4; l++) {
        k_gemm<<<gemm_blocks, 256>>>(nullptr, H, 0, Ws + (l - 1) * H * H);
        k_agg<<<agg_blocks, 256>>>(l, l < 3 ? 1 : 0);
    }

    k_pool<<<agg_blocks, 256>>>();
    k_head<<<(N_GRAPHSX * 32 + 255) / 256, 256>>>(headW, headb, out);
}

// round 4
// speedup vs baseline: 1.3062x; 1.3062x over previous
#include <cuda_runtime.h>

#define N_NODES   100000
#define N_EDGES   1600000
#define N_TOT     1700000   // edges + self loops
#define N_GRAPHSX 2048
#define H         100
#define H4        25        // H / 4 (float4 groups)
#define K0        33
#define K0P       36        // padded layer-0 width
#define BN_EPS    1e-5f
#define NBLK_SCAN 98        // ceil(100000/1024)

// ---------------- scratch (static device globals; no allocs) ----------------
__device__ __align__(16) float g_bufA[N_NODES * H];   // ping
__device__ __align__(16) float g_bufB[N_NODES * H];   // pong
__device__ __align__(16) float g_bnS[4 * H];
__device__ __align__(16) float g_bnT[4 * H];
__device__ float g_dis[N_NODES];
__device__ int   g_colptr[N_NODES + 1];
__device__ int   g_cursor[N_NODES];
__device__ int   g_csrsrc[N_TOT];
__device__ int   g_src[N_EDGES];
__device__ int   g_dst[N_EDGES];
__device__ int   g_batch[N_NODES];
__device__ int   g_gptr[N_GRAPHSX + 1];
__device__ int   g_bsum[128];
__device__ int   g_boff[128];
__device__ int   g_is64;

// ---------------- dtype probe + conversion ----------------
__global__ void k_probe(const unsigned* __restrict__ ebuf) {
    if (threadIdx.x == 0) {
        int all0 = 1;
        for (int i = 1; i < 128; i += 2) all0 &= (ebuf[i] == 0u);
        g_is64 = all0;
    }
}

__global__ void k_init() {
    int i = blockIdx.x * blockDim.x + threadIdx.x;
    if (i < N_NODES) g_cursor[i] = 1;           // self loop counted
}

// convert edges + count degrees in one pass
__global__ void k_cvt_edges(const void* __restrict__ ebuf) {
    int e = blockIdx.x * blockDim.x + threadIdx.x;
    if (e >= N_EDGES) return;
    int s, d;
    if (g_is64) {
        const long long* p = (const long long*)ebuf;
        s = (int)p[e]; d = (int)p[N_EDGES + e];
    } else {
        const int* p = (const int*)ebuf;
        s = p[e]; d = p[N_EDGES + e];
    }
    g_src[e] = s; g_dst[e] = d;
    atomicAdd(&g_cursor[d], 1);
}

__global__ void k_cvt_batch(const void* __restrict__ bbuf) {
    int i = blockIdx.x * blockDim.x + threadIdx.x;
    if (i >= N_NODES) return;
    g_batch[i] = g_is64 ? (int)((const long long*)bbuf)[i] : ((const int*)bbuf)[i];
}

// graph boundary pointers (batch is sorted)
__global__ void k_gptr() {
    int i = blockIdx.x * blockDim.x + threadIdx.x;
    if (i >= N_NODES) return;
    int b = g_batch[i];
    if (i == 0) {
        for (int g = 0; g <= b; g++) g_gptr[g] = 0;
    } else {
        int p = g_batch[i - 1];
        for (int g = p + 1; g <= b; g++) g_gptr[g] = i;
    }
    if (i == N_NODES - 1) {
        for (int g = b + 1; g <= N_GRAPHSX; g++) g_gptr[g] = N_NODES;
    }
}

// ---------------- scans ----------------
__global__ void k_scan_a() {
    __shared__ int red[256];
    int b = blockIdx.x, t = threadIdx.x;
    int base = b * 1024 + t * 4;
    int s = 0;
#pragma unroll
    for (int j = 0; j < 4; j++) {
        int idx = base + j;
        if (idx < N_NODES) {
            int c = g_cursor[idx];
            s += c;
            g_dis[idx] = rsqrtf((float)c);
        }
    }
    red[t] = s; __syncthreads();
    for (int off = 128; off > 0; off >>= 1) {
        if (t < off) red[t] += red[t + off];
        __syncthreads();
    }
    if (t == 0) g_bsum[b] = red[0];
}

__global__ void k_scan_b() {
    if (threadIdx.x == 0) {
        int acc = 0;
        for (int i = 0; i < NBLK_SCAN; i++) { g_boff[i] = acc; acc += g_bsum[i]; }
        g_colptr[N_NODES] = acc;
    }
}

// exclusive scan + self-loop fill fused
__global__ void k_scan_c() {
    __shared__ int wsum[8], woff[8];
    int b = blockIdx.x, t = threadIdx.x;
    int base = b * 1024 + t * 4;
    int v[4];
#pragma unroll
    for (int j = 0; j < 4; j++) {
        int idx = base + j;
        v[j] = (idx < N_NODES) ? g_cursor[idx] : 0;
    }
    int s = v[0] + v[1] + v[2] + v[3];
    int lane = t & 31, w = t >> 5;
    int x = s;
#pragma unroll
    for (int off = 1; off < 32; off <<= 1) {
        int y = __shfl_up_sync(0xffffffffu, x, off);
        if (lane >= off) x += y;
    }
    if (lane == 31) wsum[w] = x;
    __syncthreads();
    if (t == 0) { int a = 0; for (int i = 0; i < 8; i++) { woff[i] = a; a += wsum[i]; } }
    __syncthreads();
    int excl = (x - s) + woff[w] + g_boff[b];
#pragma unroll
    for (int j = 0; j < 4; j++) {
        int idx = base + j;
        if (idx < N_NODES) {
            g_colptr[idx] = excl;
            g_csrsrc[excl] = idx;      // self loop at slot 0
            g_cursor[idx] = excl + 1;  // fill cursor
        }
        excl += v[j];
    }
}

__global__ void k_filledges() {
    int e = blockIdx.x * blockDim.x + threadIdx.x;
    if (e < N_EDGES) {
        int p = atomicAdd(&g_cursor[g_dst[e]], 1);
        g_csrsrc[p] = g_src[e];
    }
}

__global__ void k_bnprep(const float* __restrict__ bias, const float* __restrict__ gamma,
                         const float* __restrict__ beta, const float* __restrict__ mean,
                         const float* __restrict__ var) {
    int i = blockIdx.x * blockDim.x + threadIdx.x;
    if (i < 4 * H) {
        float s = gamma[i] * rsqrtf(var[i] + BN_EPS);
        g_bnS[i] = s;
        g_bnT[i] = (bias[i] - mean[i]) * s + beta[i];
    }
}

// ---------------- layer-0 reorder: prescale x by dis -> bufA [N,36] --------
__global__ void k_prescale(const float* __restrict__ x) {
    int i = blockIdx.x * blockDim.x + threadIdx.x;
    if (i >= N_NODES * K0P) return;
    int n = i / K0P, c = i % K0P;
    g_bufA[n * K0P + c] = (c < K0) ? g_dis[n] * x[n * K0 + c] : 0.f;
}

// aggregate 36-col rows: bufA -> bufB, out = dis[n]*sum (warp/node, lanes 0..8)
__global__ void k_agg0() {
    int gwarp = (blockIdx.x * blockDim.x + threadIdx.x) >> 5;
    int lane = threadIdx.x & 31;
    if (gwarp >= N_NODES || lane >= 9) return;
    int n = gwarp;
    int beg = g_colptr[n], end = g_colptr[n + 1];
    const float4* Y4 = (const float4*)g_bufA;
    float ax = 0.f, ay = 0.f, az = 0.f, aw = 0.f;
    float bx = 0.f, by = 0.f, bz = 0.f, bw = 0.f;
    int i = beg;
    for (; i + 1 < end; i += 2) {
        int s0 = g_csrsrc[i], s1 = g_csrsrc[i + 1];
        float4 f0 = Y4[s0 * 9 + lane];
        float4 f1 = Y4[s1 * 9 + lane];
        ax += f0.x; ay += f0.y; az += f0.z; aw += f0.w;
        bx += f1.x; by += f1.y; bz += f1.z; bw += f1.w;
    }
    if (i < end) {
        int s0 = g_csrsrc[i];
        float4 f0 = Y4[s0 * 9 + lane];
        ax += f0.x; ay += f0.y; az += f0.z; aw += f0.w;
    }
    float d = g_dis[n];
    float4 o = make_float4((ax + bx) * d, (ay + by) * d, (az + bz) * d, (aw + bw) * d);
    ((float4*)g_bufB)[n * 9 + lane] = o;
}

// ---------------- GEMM: BM=64, BN=112, BK=50, 224 threads, 4x8/thread ------
// MODE 0: A=bufB [N,36] (layer-0 aggregated), epi = BN0+ReLU -> bufA [N,100]
// MODE 1: A=bufA [N,100], epi = *dis -> bufB [N,100]
template <int MODE>
__global__ void k_gemm(const float* __restrict__ W, int KA, int KW) {
    const float* A = (MODE == 0) ? g_bufB : g_bufA;
    float* O       = (MODE == 0) ? g_bufA : g_bufB;
    const int lda  = (MODE == 0) ? K0P : H;
    __shared__ float As[50][68];
    __shared__ float Wsm[50][112];
    int row0 = blockIdx.x * 64;
    int t = threadIdx.x;
    int ri = t / 14, ci = t % 14;        // 16 row-groups x 14 col-groups
    float acc[4][8];
#pragma unroll
    for (int r = 0; r < 4; r++)
#pragma unroll
        for (int c = 0; c < 8; c++) acc[r][c] = 0.f;

    for (int kt = 0; kt < KA; kt += 50) {
        for (int i = t; i < 64 * 50; i += 224) {
            int r = i / 50, k = i % 50;
            int gr = row0 + r, gk = kt + k;
            As[k][r] = (gr < N_NODES && gk < KA) ? A[gr * lda + gk] : 0.f;
        }
        for (int i = t; i < 50 * 112; i += 224) {
            int k = i / 112, c = i % 112;
            int gk = kt + k;
            Wsm[k][c] = (gk < KW && c < H) ? W[gk * H + c] : 0.f;
        }
        __syncthreads();
#pragma unroll 10
        for (int k = 0; k < 50; k++) {
            float4 a4 = *(const float4*)&As[k][ri * 4];
            float4 w0 = *(const float4*)&Wsm[k][ci * 8];
            float4 w1 = *(const float4*)&Wsm[k][ci * 8 + 4];
            float av[4] = {a4.x, a4.y, a4.z, a4.w};
            float wv[8] = {w0.x, w0.y, w0.z, w0.w, w1.x, w1.y, w1.z, w1.w};
#pragma unroll
            for (int r = 0; r < 4; r++)
#pragma unroll
                for (int c = 0; c < 8; c++)
                    acc[r][c] = fmaf(av[r], wv[c], acc[r][c]);
        }
        __syncthreads();
    }

    int c0 = ci * 8;
    if (MODE == 0) {
        float4 S0, T0, S1, T1;
        if (c0 < H)     { S0 = *(const float4*)&g_bnS[c0];     T0 = *(const float4*)&g_bnT[c0]; }
        if (c0 + 4 < H) { S1 = *(const float4*)&g_bnS[c0 + 4]; T1 = *(const float4*)&g_bnT[c0 + 4]; }
#pragma unroll
        for (int r = 0; r < 4; r++) {
            int gr = row0 + ri * 4 + r;
            if (gr >= N_NODES) break;
            if (c0 < H) {
                float4 o;
                o.x = fmaxf(fmaf(acc[r][0], S0.x, T0.x), 0.f);
                o.y = fmaxf(fmaf(acc[r][1], S0.y, T0.y), 0.f);
                o.z = fmaxf(fmaf(acc[r][2], S0.z, T0.z), 0.f);
                o.w = fmaxf(fmaf(acc[r][3], S0.w, T0.w), 0.f);
                *(float4*)&O[gr * H + c0] = o;
            }
            if (c0 + 4 < H) {
                float4 o;
                o.x = fmaxf(fmaf(acc[r][4], S1.x, T1.x), 0.f);
                o.y = fmaxf(fmaf(acc[r][5], S1.y, T1.y), 0.f);
                o.z = fmaxf(fmaf(acc[r][6], S1.z, T1.z), 0.f);
                o.w = fmaxf(fmaf(acc[r][7], S1.w, T1.w), 0.f);
                *(float4*)&O[gr * H + c0 + 4] = o;
            }
        }
    } else {
#pragma unroll
        for (int r = 0; r < 4; r++) {
            int gr = row0 + ri * 4 + r;
            if (gr >= N_NODES) break;
            float d = g_dis[gr];
            if (c0 < H) {
                float4 o = make_float4(acc[r][0] * d, acc[r][1] * d, acc[r][2] * d, acc[r][3] * d);
                *(float4*)&O[gr * H + c0] = o;
            }
            if (c0 + 4 < H) {
                float4 o = make_float4(acc[r][4] * d, acc[r][5] * d, acc[r][6] * d, acc[r][7] * d);
                *(float4*)&O[gr * H + c0 + 4] = o;
            }
        }
    }
}

// ---------------- aggregation layers 1-3: bufB -> bufA ---------------------
__global__ void k_agg(int layer, int relu) {
    int gwarp = (blockIdx.x * blockDim.x + threadIdx.x) >> 5;
    int lane = threadIdx.x & 31;
    if (gwarp >= N_NODES || lane >= H4) return;
    int n = gwarp;
    int beg = g_colptr[n], end = g_colptr[n + 1];
    const float4* Y4 = (const float4*)g_bufB;
    float a0x=0.f,a0y=0.f,a0z=0.f,a0w=0.f;
    float a1x=0.f,a1y=0.f,a1z=0.f,a1w=0.f;
    float a2x=0.f,a2y=0.f,a2z=0.f,a2w=0.f;
    float a3x=0.f,a3y=0.f,a3z=0.f,a3w=0.f;
    int i = beg;
    for (; i + 3 < end; i += 4) {
        int s0 = g_csrsrc[i], s1 = g_csrsrc[i+1], s2 = g_csrsrc[i+2], s3 = g_csrsrc[i+3];
        float4 f0 = Y4[s0 * H4 + lane];
        float4 f1 = Y4[s1 * H4 + lane];
        float4 f2 = Y4[s2 * H4 + lane];
        float4 f3 = Y4[s3 * H4 + lane];
        a0x += f0.x; a0y += f0.y; a0z += f0.z; a0w += f0.w;
        a1x += f1.x; a1y += f1.y; a1z += f1.z; a1w += f1.w;
        a2x += f2.x; a2y += f2.y; a2z += f2.z; a2w += f2.w;
        a3x += f3.x; a3y += f3.y; a3z += f3.z; a3w += f3.w;
    }
    for (; i < end; i++) {
        int s0 = g_csrsrc[i];
        float4 f0 = Y4[s0 * H4 + lane];
        a0x += f0.x; a0y += f0.y; a0z += f0.z; a0w += f0.w;
    }
    float ax = (a0x + a1x) + (a2x + a3x);
    float ay = (a0y + a1y) + (a2y + a3y);
    float az = (a0z + a1z) + (a2z + a3z);
    float aw = (a0w + a1w) + (a2w + a3w);
    float d = g_dis[n];
    int c = layer * H + lane * 4;
    float4 S = *(const float4*)&g_bnS[c];
    float4 T = *(const float4*)&g_bnT[c];
    float4 o;
    o.x = fmaf(ax * d, S.x, T.x);
    o.y = fmaf(ay * d, S.y, T.y);
    o.z = fmaf(az * d, S.z, T.z);
    o.w = fmaf(aw * d, S.w, T.w);
    if (relu) {
        o.x = fmaxf(o.x, 0.f); o.y = fmaxf(o.y, 0.f);
        o.z = fmaxf(o.z, 0.f); o.w = fmaxf(o.w, 0.f);
    }
    ((float4*)g_bufA)[n * H4 + lane] = o;
}

// ---------------- fused pool + head (block per graph, no atomics) ----------
__global__ void k_poolhead(const float* __restrict__ hW, const float* __restrict__ hb,
                           float* __restrict__ out) {
    __shared__ float wred[4];
    int g = blockIdx.x;
    int lo = g_gptr[g], hi = g_gptr[g + 1];
    int t = threadIdx.x, lane = t & 31, wid = t >> 5;
    float4 w4 = make_float4(0.f, 0.f, 0.f, 0.f);
    if (lane < H4) w4 = ((const float4*)hW)[lane];
    float s = 0.f;
    const float4* A4 = (const float4*)g_bufA;
    for (int r = lo + wid; r < hi; r += 4) {
        if (lane < H4) {
            float4 h4 = A4[r * H4 + lane];
            s += h4.x * w4.x + h4.y * w4.y + h4.z * w4.z + h4.w * w4.w;
        }
    }
#pragma unroll
    for (int off = 16; off > 0; off >>= 1)
        s += __shfl_down_sync(0xffffffffu, s, off);
    if (lane == 0) wred[wid] = s;
    __syncthreads();
    if (t == 0) {
        float tot = (wred[0] + wred[1]) + (wred[2] + wred[3]) + hb[0];
        out[g] = (tot >= 0.f) ? tot : 0.1f * tot;
    }
}

// ---------------- launch ----------------
extern "C" void kernel_launch(void* const* d_in, const int* in_sizes, int n_in,
                              void* d_out, int out_size) {
    const float* x      = (const float*)d_in[0];
    const void*  ei     = d_in[1];
    const void*  batch  = d_in[2];
    const float* W0     = (const float*)d_in[3];
    const float* Ws     = (const float*)d_in[4];
    const float* biases = (const float*)d_in[5];
    const float* gamma  = (const float*)d_in[6];
    const float* beta   = (const float*)d_in[7];
    const float* mean   = (const float*)d_in[8];
    const float* var    = (const float*)d_in[9];
    const float* headW  = (const float*)d_in[10];
    const float* headb  = (const float*)d_in[11];
    float* out = (float*)d_out;

    k_init<<<(N_NODES + 255) / 256, 256>>>();
    k_probe<<<1, 32>>>((const unsigned*)ei);
    k_cvt_edges<<<(N_EDGES + 255) / 256, 256>>>(ei);
    k_cvt_batch<<<(N_NODES + 255) / 256, 256>>>(batch);
    k_gptr<<<(N_NODES + 255) / 256, 256>>>();
    k_scan_a<<<NBLK_SCAN, 256>>>();
    k_scan_b<<<1, 32>>>();
    k_scan_c<<<NBLK_SCAN, 256>>>();
    k_filledges<<<(N_EDGES + 255) / 256, 256>>>();
    k_bnprep<<<2, 256>>>(biases, gamma, beta, mean, var);

    int gemm_blocks = (N_NODES + 63) / 64;
    int agg_blocks  = (N_NODES * 32 + 255) / 256;

    // layer 0 (reordered): prescale -> aggregate(33) -> GEMM(BN+ReLU)
    k_prescale<<<(N_NODES * K0P + 255) / 256, 256>>>(x);
    k_agg0<<<agg_blocks, 256>>>();
    k_gemm<0><<<gemm_blocks, 224>>>(W0, K0P, K0);
    // layers 1..3
    for (int l = 1; l < 4; l++) {
        k_gemm<1><<<gemm_blocks, 224>>>(Ws + (l - 1) * H * H, H, H);
        k_agg<<<agg_blocks, 256>>>(l, l < 3 ? 1 : 0);
    }

    k_poolhead<<<N_GRAPHSX, 128>>>(headW, headb, out);
}

// round 6
// speedup vs baseline: 1.4760x; 1.1300x over previous
#include <cuda_runtime.h>
#include <cuda_fp16.h>

#define N_NODES   100000
#define N_EDGES   1600000
#define N_TOT     1700000
#define N_GRAPHSX 2048
#define H         100
#define H4        25
#define K0        33
#define K0P       36
#define BN_EPS    1e-5f
#define NBLK_SCAN 98

// ---------------- scratch ----------------
__device__ __align__(16) float g_bufA[N_NODES * H];   // h (fp32)
__device__ __align__(16) float g_bufB[N_NODES * H];   // Y (fp16 for layers 1-3, fp32 36-col for layer 0)
__device__ __align__(16) float g_bnS[4 * H];
__device__ __align__(16) float g_bnT[4 * H];
__device__ float g_dis[N_NODES];
__device__ int   g_colptr[N_NODES + 1];
__device__ int   g_cursor[N_NODES];
__device__ int   g_csrsrc[N_TOT];
__device__ int   g_src[N_EDGES];
__device__ int   g_dst[N_EDGES];
__device__ int   g_gptr[N_GRAPHSX + 1];
__device__ int   g_bsum[128];
__device__ int   g_boff[128];
__device__ int   g_is64;

// ---------------- init + dtype probe (fused) ----------------
__global__ void k_init(const unsigned* __restrict__ ebuf) {
    int i = blockIdx.x * blockDim.x + threadIdx.x;
    if (i < N_NODES) g_cursor[i] = 1;
    if (i == 0) {
        int all0 = 1;
        for (int j = 1; j < 128; j += 2) all0 &= (ebuf[j] == 0u);
        g_is64 = all0;
    }
}

__global__ void k_cvt_edges(const void* __restrict__ ebuf) {
    int e = blockIdx.x * blockDim.x + threadIdx.x;
    if (e >= N_EDGES) return;
    int s, d;
    if (g_is64) {
        const long long* p = (const long long*)ebuf;
        s = (int)p[e]; d = (int)p[N_EDGES + e];
    } else {
        const int* p = (const int*)ebuf;
        s = p[e]; d = p[N_EDGES + e];
    }
    g_src[e] = s; g_dst[e] = d;
    atomicAdd(&g_cursor[d], 1);
}

// batch conversion + graph boundaries (fused; batch is sorted)
__global__ void k_gptr(const void* __restrict__ bbuf) {
    int i = blockIdx.x * blockDim.x + threadIdx.x;
    if (i >= N_NODES) return;
    int is64 = g_is64;
    int b = is64 ? (int)((const long long*)bbuf)[i] : ((const int*)bbuf)[i];
    if (i == 0) {
        for (int g = 0; g <= b; g++) g_gptr[g] = 0;
    } else {
        int p = is64 ? (int)((const long long*)bbuf)[i - 1] : ((const int*)bbuf)[i - 1];
        for (int g = p + 1; g <= b; g++) g_gptr[g] = i;
    }
    if (i == N_NODES - 1) {
        for (int g = b + 1; g <= N_GRAPHSX; g++) g_gptr[g] = N_NODES;
    }
}

// ---------------- scans ----------------
__global__ void k_scan_a() {
    __shared__ int red[256];
    int b = blockIdx.x, t = threadIdx.x;
    int base = b * 1024 + t * 4;
    int s = 0;
#pragma unroll
    for (int j = 0; j < 4; j++) {
        int idx = base + j;
        if (idx < N_NODES) {
            int c = g_cursor[idx];
            s += c;
            g_dis[idx] = rsqrtf((float)c);
        }
    }
    red[t] = s; __syncthreads();
    for (int off = 128; off > 0; off >>= 1) {
        if (t < off) red[t] += red[t + off];
        __syncthreads();
    }
    if (t == 0) g_bsum[b] = red[0];
}

__global__ void k_scan_b() {
    if (threadIdx.x == 0) {
        int acc = 0;
        for (int i = 0; i < NBLK_SCAN; i++) { g_boff[i] = acc; acc += g_bsum[i]; }
        g_colptr[N_NODES] = acc;
    }
}

__global__ void k_scan_c() {
    __shared__ int wsum[8], woff[8];
    int b = blockIdx.x, t = threadIdx.x;
    int base = b * 1024 + t * 4;
    int v[4];
#pragma unroll
    for (int j = 0; j < 4; j++) {
        int idx = base + j;
        v[j] = (idx < N_NODES) ? g_cursor[idx] : 0;
    }
    int s = v[0] + v[1] + v[2] + v[3];
    int lane = t & 31, w = t >> 5;
    int x = s;
#pragma unroll
    for (int off = 1; off < 32; off <<= 1) {
        int y = __shfl_up_sync(0xffffffffu, x, off);
        if (lane >= off) x += y;
    }
    if (lane == 31) wsum[w] = x;
    __syncthreads();
    if (t == 0) { int a = 0; for (int i = 0; i < 8; i++) { woff[i] = a; a += wsum[i]; } }
    __syncthreads();
    int excl = (x - s) + woff[w] + g_boff[b];
#pragma unroll
    for (int j = 0; j < 4; j++) {
        int idx = base + j;
        if (idx < N_NODES) {
            g_colptr[idx] = excl;
            g_csrsrc[excl] = idx;      // self loop
            g_cursor[idx] = excl + 1;
        }
        excl += v[j];
    }
}

__global__ void k_filledges() {
    int e = blockIdx.x * blockDim.x + threadIdx.x;
    if (e < N_EDGES) {
        int p = atomicAdd(&g_cursor[g_dst[e]], 1);
        g_csrsrc[p] = g_src[e];
    }
}

__global__ void k_bnprep(const float* __restrict__ bias, const float* __restrict__ gamma,
                         const float* __restrict__ beta, const float* __restrict__ mean,
                         const float* __restrict__ var) {
    int i = blockIdx.x * blockDim.x + threadIdx.x;
    if (i < 4 * H) {
        float s = gamma[i] * rsqrtf(var[i] + BN_EPS);
        g_bnS[i] = s;
        g_bnT[i] = (bias[i] - mean[i]) * s + beta[i];
    }
}

// ---------------- layer-0: prescale x by dis -> bufA [N,36] ----------------
__global__ void k_prescale(const float* __restrict__ x) {
    int i = blockIdx.x * blockDim.x + threadIdx.x;
    if (i >= N_NODES * K0P) return;
    int n = i / K0P, c = i % K0P;
    g_bufA[n * K0P + c] = (c < K0) ? g_dis[n] * x[n * K0 + c] : 0.f;
}

// aggregate 36-col fp32 rows: bufA -> bufB (warp/node, lanes 0..8)
__global__ void k_agg0() {
    int gwarp = (blockIdx.x * blockDim.x + threadIdx.x) >> 5;
    int lane = threadIdx.x & 31;
    if (gwarp >= N_NODES || lane >= 9) return;
    int n = gwarp;
    int beg = g_colptr[n], end = g_colptr[n + 1];
    const float4* Y4 = (const float4*)g_bufA;
    float ax = 0.f, ay = 0.f, az = 0.f, aw = 0.f;
    float bx = 0.f, by = 0.f, bz = 0.f, bw = 0.f;
    int i = beg;
    for (; i + 1 < end; i += 2) {
        int s0 = g_csrsrc[i], s1 = g_csrsrc[i + 1];
        float4 f0 = Y4[s0 * 9 + lane];
        float4 f1 = Y4[s1 * 9 + lane];
        ax += f0.x; ay += f0.y; az += f0.z; aw += f0.w;
        bx += f1.x; by += f1.y; bz += f1.z; bw += f1.w;
    }
    if (i < end) {
        int s0 = g_csrsrc[i];
        float4 f0 = Y4[s0 * 9 + lane];
        ax += f0.x; ay += f0.y; az += f0.z; aw += f0.w;
    }
    float d = g_dis[n];
    float4 o = make_float4((ax + bx) * d, (ay + by) * d, (az + bz) * d, (aw + bw) * d);
    ((float4*)g_bufB)[n * 9 + lane] = o;
}

// ---------------- GEMM: BM=128, BN=100, 800 threads, 4x4 micro-tile --------
// MODE 0: A=bufB [N,36] fp32 -> O=bufA fp32, epi = BN0+ReLU      (BK=36)
// MODE 1: A=bufA [N,100] fp32 -> Y=bufB fp16, epi = *dis          (BK=50, 2 tiles)
template <int MODE, int BK, int LDA>
__global__ void __launch_bounds__(800) k_gemm(const float* __restrict__ W, int KA, int KW) {
    const float* A = (MODE == 0) ? g_bufB : g_bufA;
    __shared__ float As[128][BK + 2];
    __shared__ float Wsm[BK][100];
    int row0 = blockIdx.x * 128;
    int t = threadIdx.x;
    int ri = t / 25, ci = t % 25;        // 32 row-groups x 25 col-groups
    int r0 = ri * 4, c0 = ci * 4;
    float acc[4][4];
#pragma unroll
    for (int r = 0; r < 4; r++)
#pragma unroll
        for (int c = 0; c < 4; c++) acc[r][c] = 0.f;

    for (int kt = 0; kt < KA; kt += BK) {
        for (int i = t; i < 128 * BK; i += 800) {
            int r = i / BK, k = i % BK;
            int gr = row0 + r;
            As[r][k] = (gr < N_NODES) ? A[gr * LDA + kt + k] : 0.f;
        }
        for (int i = t; i < BK * 100; i += 800) {
            int k = i / 100, c = i % 100;
            int gk = kt + k;
            Wsm[k][c] = (gk < KW) ? W[gk * H + c] : 0.f;
        }
        __syncthreads();
#pragma unroll 6
        for (int k = 0; k < BK; k++) {
            float a0 = As[r0 + 0][k];
            float a1 = As[r0 + 1][k];
            float a2 = As[r0 + 2][k];
            float a3 = As[r0 + 3][k];
            float4 w = *(const float4*)&Wsm[k][c0];
#pragma unroll
            for (int c = 0; c < 4; c++) {
                float wv = (&w.x)[c];
                acc[0][c] = fmaf(a0, wv, acc[0][c]);
                acc[1][c] = fmaf(a1, wv, acc[1][c]);
                acc[2][c] = fmaf(a2, wv, acc[2][c]);
                acc[3][c] = fmaf(a3, wv, acc[3][c]);
            }
        }
        __syncthreads();
    }

    if (MODE == 0) {
        float4 S = *(const float4*)&g_bnS[c0];
        float4 T = *(const float4*)&g_bnT[c0];
#pragma unroll
        for (int r = 0; r < 4; r++) {
            int gr = row0 + r0 + r;
            if (gr >= N_NODES) break;
            float4 o;
            o.x = fmaxf(fmaf(acc[r][0], S.x, T.x), 0.f);
            o.y = fmaxf(fmaf(acc[r][1], S.y, T.y), 0.f);
            o.z = fmaxf(fmaf(acc[r][2], S.z, T.z), 0.f);
            o.w = fmaxf(fmaf(acc[r][3], S.w, T.w), 0.f);
            *(float4*)&g_bufA[gr * H + c0] = o;
        }
    } else {
        __half* Yh = (__half*)g_bufB;
#pragma unroll
        for (int r = 0; r < 4; r++) {
            int gr = row0 + r0 + r;
            if (gr >= N_NODES) break;
            float d = g_dis[gr];
            __half2 h0 = __floats2half2_rn(acc[r][0] * d, acc[r][1] * d);
            __half2 h1 = __floats2half2_rn(acc[r][2] * d, acc[r][3] * d);
            uint2 u;
            u.x = *(unsigned*)&h0;
            u.y = *(unsigned*)&h1;
            *(uint2*)&Yh[gr * H + c0] = u;
        }
    }
}

// ---------------- aggregation layers 1-3: bufB(fp16) -> bufA(fp32) ---------
__global__ void k_agg(int layer, int relu) {
    int gwarp = (blockIdx.x * blockDim.x + threadIdx.x) >> 5;
    int lane = threadIdx.x & 31;
    if (gwarp >= N_NODES || lane >= H4) return;
    int n = gwarp;
    int beg = g_colptr[n], end = g_colptr[n + 1];
    const uint2* Y2 = (const uint2*)g_bufB;    // 25 uint2 per row (100 halves)
    float a0x=0.f,a0y=0.f,a0z=0.f,a0w=0.f;
    float a1x=0.f,a1y=0.f,a1z=0.f,a1w=0.f;
    float a2x=0.f,a2y=0.f,a2z=0.f,a2w=0.f;
    float a3x=0.f,a3y=0.f,a3z=0.f,a3w=0.f;
    int i = beg;
    for (; i + 3 < end; i += 4) {
        int s0 = g_csrsrc[i], s1 = g_csrsrc[i+1], s2 = g_csrsrc[i+2], s3 = g_csrsrc[i+3];
        uint2 u0 = Y2[s0 * H4 + lane];
        uint2 u1 = Y2[s1 * H4 + lane];
        uint2 u2 = Y2[s2 * H4 + lane];
        uint2 u3 = Y2[s3 * H4 + lane];
        float2 p; 
        p = __half22float2(*(__half2*)&u0.x); a0x += p.x; a0y += p.y;
        p = __half22float2(*(__half2*)&u0.y); a0z += p.x; a0w += p.y;
        p = __half22float2(*(__half2*)&u1.x); a1x += p.x; a1y += p.y;
        p = __half22float2(*(__half2*)&u1.y); a1z += p.x; a1w += p.y;
        p = __half22float2(*(__half2*)&u2.x); a2x += p.x; a2y += p.y;
        p = __half22float2(*(__half2*)&u2.y); a2z += p.x; a2w += p.y;
        p = __half22float2(*(__half2*)&u3.x); a3x += p.x; a3y += p.y;
        p = __half22float2(*(__half2*)&u3.y); a3z += p.x; a3w += p.y;
    }
    for (; i < end; i++) {
        int s0 = g_csrsrc[i];
        uint2 u0 = Y2[s0 * H4 + lane];
        float2 p;
        p = __half22float2(*(__half2*)&u0.x); a0x += p.x; a0y += p.y;
        p = __half22float2(*(__half2*)&u0.y); a0z += p.x; a0w += p.y;
    }
    float ax = (a0x + a1x) + (a2x + a3x);
    float ay = (a0y + a1y) + (a2y + a3y);
    float az = (a0z + a1z) + (a2z + a3z);
    float aw = (a0w + a1w) + (a2w + a3w);
    float d = g_dis[n];
    int c = layer * H + lane * 4;
    float4 S = *(const float4*)&g_bnS[c];
    float4 T = *(const float4*)&g_bnT[c];
    float4 o;
    o.x = fmaf(ax * d, S.x, T.x);
    o.y = fmaf(ay * d, S.y, T.y);
    o.z = fmaf(az * d, S.z, T.z);
    o.w = fmaf(aw * d, S.w, T.w);
    if (relu) {
        o.x = fmaxf(o.x, 0.f); o.y = fmaxf(o.y, 0.f);
        o.z = fmaxf(o.z, 0.f); o.w = fmaxf(o.w, 0.f);
    }
    ((float4*)g_bufA)[n * H4 + lane] = o;
}

// ---------------- fused pool + head ----------------
__global__ void k_poolhead(const float* __restrict__ hW, const float* __restrict__ hb,
                           float* __restrict__ out) {
    __shared__ float wred[4];
    int g = blockIdx.x;
    int lo = g_gptr[g], hi = g_gptr[g + 1];
    int t = threadIdx.x, lane = t & 31, wid = t >> 5;
    float4 w4 = make_float4(0.f, 0.f, 0.f, 0.f);
    if (lane < H4) w4 = ((const float4*)hW)[lane];
    float s = 0.f;
    const float4* A4 = (const float4*)g_bufA;
    for (int r = lo + wid; r < hi; r += 4) {
        if (lane < H4) {
            float4 h4 = A4[r * H4 + lane];
            s += h4.x * w4.x + h4.y * w4.y + h4.z * w4.z + h4.w * w4.w;
        }
    }
#pragma unroll
    for (int off = 16; off > 0; off >>= 1)
        s += __shfl_down_sync(0xffffffffu, s, off);
    if (lane == 0) wred[wid] = s;
    __syncthreads();
    if (t == 0) {
        float tot = (wred[0] + wred[1]) + (wred[2] + wred[3]) + hb[0];
        out[g] = (tot >= 0.f) ? tot : 0.1f * tot;
    }
}

// ---------------- launch ----------------
extern "C" void kernel_launch(void* const* d_in, const int* in_sizes, int n_in,
                              void* d_out, int out_size) {
    const float* x      = (const float*)d_in[0];
    const void*  ei     = d_in[1];
    const void*  batch  = d_in[2];
    const float* W0     = (const float*)d_in[3];
    const float* Ws     = (const float*)d_in[4];
    const float* biases = (const float*)d_in[5];
    const float* gamma  = (const float*)d_in[6];
    const float* beta   = (const float*)d_in[7];
    const float* mean   = (const float*)d_in[8];
    const float* var    = (const float*)d_in[9];
    const float* headW  = (const float*)d_in[10];
    const float* headb  = (const float*)d_in[11];
    float* out = (float*)d_out;

    k_init<<<(N_NODES + 255) / 256, 256>>>((const unsigned*)ei);
    k_cvt_edges<<<(N_EDGES + 255) / 256, 256>>>(ei);
    k_gptr<<<(N_NODES + 255) / 256, 256>>>(batch);
    k_scan_a<<<NBLK_SCAN, 256>>>();
    k_scan_b<<<1, 32>>>();
    k_scan_c<<<NBLK_SCAN, 256>>>();
    k_filledges<<<(N_EDGES + 255) / 256, 256>>>();
    k_bnprep<<<2, 256>>>(biases, gamma, beta, mean, var);

    int gemm_blocks = (N_NODES + 127) / 128;
    int agg_blocks  = (N_NODES * 32 + 255) / 256;

    // layer 0 (reordered): prescale -> aggregate(36) -> GEMM(BN+ReLU)
    k_prescale<<<(N_NODES * K0P + 255) / 256, 256>>>(x);
    k_agg0<<<agg_blocks, 256>>>();
    k_gemm<0, 36, K0P><<<gemm_blocks, 800>>>(W0, K0P, K0);
    // layers 1..3
    for (int l = 1; l < 4; l++) {
        k_gemm<1, 50, H><<<gemm_blocks, 800>>>(Ws + (l - 1) * H * H, H, H);
        k_agg<<<agg_blocks, 256>>>(l, l < 3 ? 1 : 0);
    }

    k_poolhead<<<N_GRAPHSX, 128>>>(headW, headb, out);
}

// round 7
// speedup vs baseline: 2.2898x; 1.5514x over previous
#include <cuda_runtime.h>
#include <cuda_fp16.h>

#define N_NODES   100000
#define N_EDGES   1600000
#define N_TOT     1700000
#define N_GRAPHSX 2048
#define H         100
#define H4        25
#define K0        33
#define K0P       36
#define BN_EPS    1e-5f
#define NBLK_SCAN 98

// ---------------- scratch ----------------
__device__ __align__(16) float  g_x36[N_NODES * K0P];   // prescaled x (fp32)
__device__ __align__(16) __half g_hx[N_NODES * K0P];    // aggregated x (fp16) -> GEMM0 input
__device__ __align__(16) __half g_h[N_NODES * H];       // h (fp16)
__device__ __align__(16) __half g_Y[N_NODES * H];       // Y = dis*(h@W) (fp16)
__device__ __align__(16) __half g_Wh[104 * 112];        // transposed fp16 weight staging
__device__ __align__(16) float  g_bnS[4 * H];
__device__ __align__(16) float  g_bnT[4 * H];
__device__ float g_dis[N_NODES];
__device__ int   g_colptr[N_NODES + 1];
__device__ int   g_cursor[N_NODES];
__device__ int   g_csrsrc[N_TOT];
__device__ int   g_src[N_EDGES];
__device__ int   g_dst[N_EDGES];
__device__ int   g_gptr[N_GRAPHSX + 1];
__device__ int   g_bsum[128];
__device__ int   g_boff[128];
__device__ int   g_is64;

// ---------------- init + dtype probe ----------------
__global__ void k_init(const unsigned* __restrict__ ebuf) {
    int i = blockIdx.x * blockDim.x + threadIdx.x;
    if (i < N_NODES) g_cursor[i] = 1;
    if (i == 0) {
        int all0 = 1;
        for (int j = 1; j < 128; j += 2) all0 &= (ebuf[j] == 0u);
        g_is64 = all0;
    }
}

__global__ void k_cvt_edges(const void* __restrict__ ebuf) {
    int e = blockIdx.x * blockDim.x + threadIdx.x;
    if (e >= N_EDGES) return;
    int s, d;
    if (g_is64) {
        const long long* p = (const long long*)ebuf;
        s = (int)p[e]; d = (int)p[N_EDGES + e];
    } else {
        const int* p = (const int*)ebuf;
        s = p[e]; d = p[N_EDGES + e];
    }
    g_src[e] = s; g_dst[e] = d;
    atomicAdd(&g_cursor[d], 1);
}

__global__ void k_gptr(const void* __restrict__ bbuf) {
    int i = blockIdx.x * blockDim.x + threadIdx.x;
    if (i >= N_NODES) return;
    int is64 = g_is64;
    int b = is64 ? (int)((const long long*)bbuf)[i] : ((const int*)bbuf)[i];
    if (i == 0) {
        for (int g = 0; g <= b; g++) g_gptr[g] = 0;
    } else {
        int p = is64 ? (int)((const long long*)bbuf)[i - 1] : ((const int*)bbuf)[i - 1];
        for (int g = p + 1; g <= b; g++) g_gptr[g] = i;
    }
    if (i == N_NODES - 1) {
        for (int g = b + 1; g <= N_GRAPHSX; g++) g_gptr[g] = N_NODES;
    }
}

// ---------------- scans ----------------
__global__ void k_scan_a() {
    __shared__ int red[256];
    int b = blockIdx.x, t = threadIdx.x;
    int base = b * 1024 + t * 4;
    int s = 0;
#pragma unroll
    for (int j = 0; j < 4; j++) {
        int idx = base + j;
        if (idx < N_NODES) {
            int c = g_cursor[idx];
            s += c;
            g_dis[idx] = rsqrtf((float)c);
        }
    }
    red[t] = s; __syncthreads();
    for (int off = 128; off > 0; off >>= 1) {
        if (t < off) red[t] += red[t + off];
        __syncthreads();
    }
    if (t == 0) g_bsum[b] = red[0];
}

// single-warp scan over 98 block sums (was serial 1-thread)
__global__ void k_scan_b() {
    int lane = threadIdx.x;
    int base = lane * 4;
    int c[4]; int s = 0;
#pragma unroll
    for (int j = 0; j < 4; j++) {
        c[j] = (base + j < NBLK_SCAN) ? g_bsum[base + j] : 0;
        s += c[j];
    }
    int x = s;
#pragma unroll
    for (int off = 1; off < 32; off <<= 1) {
        int y = __shfl_up_sync(0xffffffffu, x, off);
        if (lane >= off) x += y;
    }
    int acc = x - s;
#pragma unroll
    for (int j = 0; j < 4; j++) {
        if (base + j < NBLK_SCAN) g_boff[base + j] = acc;
        acc += c[j];
    }
    if (lane == 31) g_colptr[N_NODES] = x;
}

__global__ void k_scan_c() {
    __shared__ int wsum[8], woff[8];
    int b = blockIdx.x, t = threadIdx.x;
    int base = b * 1024 + t * 4;
    int v[4];
#pragma unroll
    for (int j = 0; j < 4; j++) {
        int idx = base + j;
        v[j] = (idx < N_NODES) ? g_cursor[idx] : 0;
    }
    int s = v[0] + v[1] + v[2] + v[3];
    int lane = t & 31, w = t >> 5;
    int x = s;
#pragma unroll
    for (int off = 1; off < 32; off <<= 1) {
        int y = __shfl_up_sync(0xffffffffu, x, off);
        if (lane >= off) x += y;
    }
    if (lane == 31) wsum[w] = x;
    __syncthreads();
    if (t == 0) { int a = 0; for (int i = 0; i < 8; i++) { woff[i] = a; a += wsum[i]; } }
    __syncthreads();
    int excl = (x - s) + woff[w] + g_boff[b];
#pragma unroll
    for (int j = 0; j < 4; j++) {
        int idx = base + j;
        if (idx < N_NODES) {
            g_colptr[idx] = excl;
            g_csrsrc[excl] = idx;      // self loop
            g_cursor[idx] = excl + 1;
        }
        excl += v[j];
    }
}

__global__ void k_filledges() {
    int e = blockIdx.x * blockDim.x + threadIdx.x;
    if (e < N_EDGES) {
        int p = atomicAdd(&g_cursor[g_dst[e]], 1);
        g_csrsrc[p] = g_src[e];
    }
}

__global__ void k_bnprep(const float* __restrict__ bias, const float* __restrict__ gamma,
                         const float* __restrict__ beta, const float* __restrict__ mean,
                         const float* __restrict__ var) {
    int i = blockIdx.x * blockDim.x + threadIdx.x;
    if (i < 4 * H) {
        float s = gamma[i] * rsqrtf(var[i] + BN_EPS);
        g_bnS[i] = s;
        g_bnT[i] = (bias[i] - mean[i]) * s + beta[i];
    }
}

// weight transpose + fp16: g_Wh[n][KP] = W[k][n], zero-padded
__global__ void k_wcvt(const float* __restrict__ W, int KA, int KP) {
    int i = blockIdx.x * blockDim.x + threadIdx.x;
    if (i >= 104 * KP) return;
    int n = i / KP, k = i % KP;
    g_Wh[i] = (n < H && k < KA) ? __float2half(W[k * H + n]) : __float2half(0.f);
}

// ---------------- layer-0: prescale x by dis -> g_x36 [N,36] fp32 ----------
__global__ void k_prescale(const float* __restrict__ x) {
    int i = blockIdx.x * blockDim.x + threadIdx.x;
    if (i >= N_NODES * K0P) return;
    int n = i / K0P, c = i % K0P;
    g_x36[n * K0P + c] = (c < K0) ? g_dis[n] * x[n * K0 + c] : 0.f;
}

// aggregate 36-col fp32 rows -> g_hx fp16 (warp/node, lanes 0..8)
__global__ void k_agg0() {
    int gwarp = (blockIdx.x * blockDim.x + threadIdx.x) >> 5;
    int lane = threadIdx.x & 31;
    if (gwarp >= N_NODES || lane >= 9) return;
    int n = gwarp;
    int beg = g_colptr[n], end = g_colptr[n + 1];
    const float4* Y4 = (const float4*)g_x36;
    float ax = 0.f, ay = 0.f, az = 0.f, aw = 0.f;
    float bx = 0.f, by = 0.f, bz = 0.f, bw = 0.f;
    int i = beg;
    for (; i + 1 < end; i += 2) {
        int s0 = g_csrsrc[i], s1 = g_csrsrc[i + 1];
        float4 f0 = Y4[s0 * 9 + lane];
        float4 f1 = Y4[s1 * 9 + lane];
        ax += f0.x; ay += f0.y; az += f0.z; aw += f0.w;
        bx += f1.x; by += f1.y; bz += f1.z; bw += f1.w;
    }
    if (i < end) {
        int s0 = g_csrsrc[i];
        float4 f0 = Y4[s0 * 9 + lane];
        ax += f0.x; ay += f0.y; az += f0.z; aw += f0.w;
    }
    float d = g_dis[n];
    __half2 h0 = __floats2half2_rn((ax + bx) * d, (ay + by) * d);
    __half2 h1 = __floats2half2_rn((az + bz) * d, (aw + bw) * d);
    uint2 u; u.x = *(unsigned*)&h0; u.y = *(unsigned*)&h1;
    *(uint2*)&g_hx[n * K0P + lane * 4] = u;
}

// ---------------- tensor-core GEMM (mma.sync m16n8k16 fp16->fp32) ----------
// BM=64 (4 warps x 16 rows), BN=104 (13 n8-tiles), whole K in smem.
// MODE 0: A=g_hx [N,36] -> h=g_h fp16, epi = BN(layer0)+ReLU
// MODE 1: A=g_h  [N,100] -> Y=g_Y fp16, epi = *dis[row]
template <int KPAD, int KA, int MODE>
__global__ void __launch_bounds__(128) k_mma() {
    constexpr int KS = KPAD + 8;            // halves per smem row (bank-stagger pad)
    constexpr int C2 = KA / 2;              // half2 per A row
    constexpr int P2 = (KPAD - KA) / 2;     // half2 of zero pad per row
    __shared__ __half As[64 * KS];
    __shared__ __half Bs[104 * KS];
    int row0 = blockIdx.x * 64;
    int tid = threadIdx.x;

    const __half* Asrc = (MODE == 0) ? g_hx : g_h;
    const __half2 z2 = __float2half2_rn(0.f);
    // fill A (coalesced half2 reads)
    for (int i = tid; i < 64 * C2; i += 128) {
        int r = i / C2, c2 = i % C2;
        int gr = row0 + r;
        __half2 v = (gr < N_NODES) ? ((const __half2*)Asrc)[gr * C2 + c2] : z2;
        *(__half2*)&As[r * KS + c2 * 2] = v;
    }
    for (int i = tid; i < 64 * P2; i += 128) {
        int r = i / P2, j = i % P2;
        *(__half2*)&As[r * KS + KA + j * 2] = z2;
    }
    // fill B from staged transposed weights
    for (int i = tid; i < 104 * (KPAD / 2); i += 128) {
        int n = i / (KPAD / 2), c2 = i % (KPAD / 2);
        __half2 v = ((const __half2*)g_Wh)[i];
        *(__half2*)&Bs[n * KS + c2 * 2] = v;
    }
    __syncthreads();

    int warp = tid >> 5, lane = tid & 31;
    int g = lane >> 2, t = lane & 3;
    int r0 = warp * 16;
    float acc[13][4];
#pragma unroll
    for (int j = 0; j < 13; j++)
#pragma unroll
        for (int c = 0; c < 4; c++) acc[j][c] = 0.f;

#pragma unroll
    for (int ks = 0; ks < KPAD / 16; ks++) {
        int kb = ks * 16 + t * 2;
        unsigned a0 = *(unsigned*)&As[(r0 + g) * KS + kb];
        unsigned a1 = *(unsigned*)&As[(r0 + g + 8) * KS + kb];
        unsigned a2 = *(unsigned*)&As[(r0 + g) * KS + kb + 8];
        unsigned a3 = *(unsigned*)&As[(r0 + g + 8) * KS + kb + 8];
#pragma unroll
        for (int j = 0; j < 13; j++) {
            int nr = j * 8 + g;
            unsigned b0 = *(unsigned*)&Bs[nr * KS + kb];
            unsigned b1 = *(unsigned*)&Bs[nr * KS + kb + 8];
            asm volatile(
                "mma.sync.aligned.m16n8k16.row.col.f32.f16.f16.f32 "
                "{%0,%1,%2,%3}, {%4,%5,%6,%7}, {%8,%9}, {%0,%1,%2,%3};"
                : "+f"(acc[j][0]), "+f"(acc[j][1]), "+f"(acc[j][2]), "+f"(acc[j][3])
                : "r"(a0), "r"(a1), "r"(a2), "r"(a3), "r"(b0), "r"(b1));
        }
    }

    int gr0 = row0 + r0 + g;
    int gr1 = gr0 + 8;
    if (MODE == 0) {
#pragma unroll
        for (int j = 0; j < 13; j++) {
            int c = j * 8 + t * 2;
            if (c >= H) continue;
            float Sx = g_bnS[c], Sy = g_bnS[c + 1];
            float Tx = g_bnT[c], Ty = g_bnT[c + 1];
            if (gr0 < N_NODES) {
                float ox = fmaxf(fmaf(acc[j][0], Sx, Tx), 0.f);
                float oy = fmaxf(fmaf(acc[j][1], Sy, Ty), 0.f);
                __half2 hv = __floats2half2_rn(ox, oy);
                *(__half2*)&g_h[gr0 * H + c] = hv;
            }
            if (gr1 < N_NODES) {
                float ox = fmaxf(fmaf(acc[j][2], Sx, Tx), 0.f);
                float oy = fmaxf(fmaf(acc[j][3], Sy, Ty), 0.f);
                __half2 hv = __floats2half2_rn(ox, oy);
                *(__half2*)&g_h[gr1 * H + c] = hv;
            }
        }
    } else {
        float d0 = (gr0 < N_NODES) ? g_dis[gr0] : 0.f;
        float d1 = (gr1 < N_NODES) ? g_dis[gr1] : 0.f;
#pragma unroll
        for (int j = 0; j < 13; j++) {
            int c = j * 8 + t * 2;
            if (c >= H) continue;
            if (gr0 < N_NODES) {
                __half2 hv = __floats2half2_rn(acc[j][0] * d0, acc[j][1] * d0);
                *(__half2*)&g_Y[gr0 * H + c] = hv;
            }
            if (gr1 < N_NODES) {
                __half2 hv = __floats2half2_rn(acc[j][2] * d1, acc[j][3] * d1);
                *(__half2*)&g_Y[gr1 * H + c] = hv;
            }
        }
    }
}

// ---------------- aggregation layers 1-3: g_Y(fp16) -> g_h(fp16) -----------
__global__ void k_agg(int layer, int relu) {
    int gwarp = (blockIdx.x * blockDim.x + threadIdx.x) >> 5;
    int lane = threadIdx.x & 31;
    if (gwarp >= N_NODES || lane >= H4) return;
    int n = gwarp;
    int beg = g_colptr[n], end = g_colptr[n + 1];
    const uint2* Y2 = (const uint2*)g_Y;
    float a0x=0.f,a0y=0.f,a0z=0.f,a0w=0.f;
    float a1x=0.f,a1y=0.f,a1z=0.f,a1w=0.f;
    float a2x=0.f,a2y=0.f,a2z=0.f,a2w=0.f;
    float a3x=0.f,a3y=0.f,a3z=0.f,a3w=0.f;
    int i = beg;
    for (; i + 3 < end; i += 4) {
        int s0 = g_csrsrc[i], s1 = g_csrsrc[i+1], s2 = g_csrsrc[i+2], s3 = g_csrsrc[i+3];
        uint2 u0 = Y2[s0 * H4 + lane];
        uint2 u1 = Y2[s1 * H4 + lane];
        uint2 u2 = Y2[s2 * H4 + lane];
        uint2 u3 = Y2[s3 * H4 + lane];
        float2 p;
        p = __half22float2(*(__half2*)&u0.x); a0x += p.x; a0y += p.y;
        p = __half22float2(*(__half2*)&u0.y); a0z += p.x; a0w += p.y;
        p = __half22float2(*(__half2*)&u1.x); a1x += p.x; a1y += p.y;
        p = __half22float2(*(__half2*)&u1.y); a1z += p.x; a1w += p.y;
        p = __half22float2(*(__half2*)&u2.x); a2x += p.x; a2y += p.y;
        p = __half22float2(*(__half2*)&u2.y); a2z += p.x; a2w += p.y;
        p = __half22float2(*(__half2*)&u3.x); a3x += p.x; a3y += p.y;
        p = __half22float2(*(__half2*)&u3.y); a3z += p.x; a3w += p.y;
    }
    for (; i < end; i++) {
        int s0 = g_csrsrc[i];
        uint2 u0 = Y2[s0 * H4 + lane];
        float2 p;
        p = __half22float2(*(__half2*)&u0.x); a0x += p.x; a0y += p.y;
        p = __half22float2(*(__half2*)&u0.y); a0z += p.x; a0w += p.y;
    }
    float ax = (a0x + a1x) + (a2x + a3x);
    float ay = (a0y + a1y) + (a2y + a3y);
    float az = (a0z + a1z) + (a2z + a3z);
    float aw = (a0w + a1w) + (a2w + a3w);
    float d = g_dis[n];
    int c = layer * H + lane * 4;
    float4 S = *(const float4*)&g_bnS[c];
    float4 T = *(const float4*)&g_bnT[c];
    float ox = fmaf(ax * d, S.x, T.x);
    float oy = fmaf(ay * d, S.y, T.y);
    float oz = fmaf(az * d, S.z, T.z);
    float ow = fmaf(aw * d, S.w, T.w);
    if (relu) {
        ox = fmaxf(ox, 0.f); oy = fmaxf(oy, 0.f);
        oz = fmaxf(oz, 0.f); ow = fmaxf(ow, 0.f);
    }
    __half2 h0 = __floats2half2_rn(ox, oy);
    __half2 h1 = __floats2half2_rn(oz, ow);
    uint2 u; u.x = *(unsigned*)&h0; u.y = *(unsigned*)&h1;
    *(uint2*)&g_h[n * H + lane * 4] = u;
}

// ---------------- fused pool + head ----------------
__global__ void k_poolhead(const float* __restrict__ hW, const float* __restrict__ hb,
                           float* __restrict__ out) {
    __shared__ float wred[4];
    int g = blockIdx.x;
    int lo = g_gptr[g], hi = g_gptr[g + 1];
    int t = threadIdx.x, lane = t & 31, wid = t >> 5;
    float4 w4 = make_float4(0.f, 0.f, 0.f, 0.f);
    if (lane < H4) w4 = ((const float4*)hW)[lane];
    float s = 0.f;
    const uint2* H2 = (const uint2*)g_h;
    for (int r = lo + wid; r < hi; r += 4) {
        if (lane < H4) {
            uint2 u = H2[r * H4 + lane];
            float2 p0 = __half22float2(*(__half2*)&u.x);
            float2 p1 = __half22float2(*(__half2*)&u.y);
            s += p0.x * w4.x + p0.y * w4.y + p1.x * w4.z + p1.y * w4.w;
        }
    }
#pragma unroll
    for (int off = 16; off > 0; off >>= 1)
        s += __shfl_down_sync(0xffffffffu, s, off);
    if (lane == 0) wred[wid] = s;
    __syncthreads();
    if (t == 0) {
        float tot = (wred[0] + wred[1]) + (wred[2] + wred[3]) + hb[0];
        out[g] = (tot >= 0.f) ? tot : 0.1f * tot;
    }
}

// ---------------- launch ----------------
extern "C" void kernel_launch(void* const* d_in, const int* in_sizes, int n_in,
                              void* d_out, int out_size) {
    const float* x      = (const float*)d_in[0];
    const void*  ei     = d_in[1];
    const void*  batch  = d_in[2];
    const float* W0     = (const float*)d_in[3];
    const float* Ws     = (const float*)d_in[4];
    const float* biases = (const float*)d_in[5];
    const float* gamma  = (const float*)d_in[6];
    const float* beta   = (const float*)d_in[7];
    const float* mean   = (const float*)d_in[8];
    const float* var    = (const float*)d_in[9];
    const float* headW  = (const float*)d_in[10];
    const float* headb  = (const float*)d_in[11];
    float* out = (float*)d_out;

    k_init<<<(N_NODES + 255) / 256, 256>>>((const unsigned*)ei);
    k_cvt_edges<<<(N_EDGES + 255) / 256, 256>>>(ei);
    k_gptr<<<(N_NODES + 255) / 256, 256>>>(batch);
    k_scan_a<<<NBLK_SCAN, 256>>>();
    k_scan_b<<<1, 32>>>();
    k_scan_c<<<NBLK_SCAN, 256>>>();
    k_filledges<<<(N_EDGES + 255) / 256, 256>>>();
    k_bnprep<<<2, 256>>>(biases, gamma, beta, mean, var);

    int mma_blocks = (N_NODES + 63) / 64;
    int agg_blocks = (N_NODES * 32 + 255) / 256;

    // layer 0: prescale -> aggregate(36, fp16 out) -> MMA GEMM (BN0+ReLU)
    k_prescale<<<(N_NODES * K0P + 255) / 256, 256>>>(x);
    k_agg0<<<agg_blocks, 256>>>();
    k_wcvt<<<(104 * 48 + 255) / 256, 256>>>(W0, K0, 48);
    k_mma<48, 36, 0><<<mma_blocks, 128>>>();
    // layers 1..3
    for (int l = 1; l < 4; l++) {
        k_wcvt<<<(104 * 112 + 255) / 256, 256>>>(Ws + (l - 1) * H * H, H, 112);
        k_mma<112, 100, 1><<<mma_blocks, 128>>>();
        k_agg<<<agg_blocks, 256>>>(l, l < 3 ? 1 : 0);
    }

    k_poolhead<<<N_GRAPHSX, 128>>>(headW, headb, out);
}

// round 9
// speedup vs baseline: 2.6378x; 1.1520x over previous
#include <cuda_runtime.h>
#include <cuda_fp16.h>

#define N_NODES   100000
#define N_EDGES   1600000
#define N_TOT     1700000
#define N_GRAPHSX 2048
#define H         100
#define H4        25
#define K0        33
#define K0P       36
#define BN_EPS    1e-5f
#define NBLK_SCAN 98
#define WSL       (104 * 112)   // weight staging slice

// ---------------- scratch ----------------
__device__ __align__(16) __half g_hx[N_NODES * K0P];    // aggregated x (fp16)
__device__ __align__(16) __half g_h[N_NODES * H];       // h (fp16)
__device__ __align__(16) __half g_Y[N_NODES * H];       // Y = dis*(h@W) (fp16)
__device__ __align__(16) __half g_Wh[4 * WSL];          // transposed fp16 weights
__device__ __align__(16) float  g_bnS[4 * H];
__device__ __align__(16) float  g_bnT[4 * H];
__device__ float g_gsum[N_GRAPHSX];
__device__ float g_dis[N_NODES];
__device__ int   g_colptr[N_NODES + 1];
__device__ int   g_cursor[N_NODES];
__device__ int   g_csrsrc[N_TOT];
__device__ int   g_batch[N_NODES];
__device__ int   g_bsum[128];
__device__ int   g_boff[128];
__device__ int   g_is64;

// ---------------- init + probe ----------------
__global__ void k_init(const unsigned* __restrict__ ebuf) {
    int i = blockIdx.x * blockDim.x + threadIdx.x;
    if (i < N_NODES) g_cursor[i] = 1;
    if (i < N_GRAPHSX) g_gsum[i] = 0.f;
    if (i == 0) {
        int all0 = 1;
        for (int j = 1; j < 128; j += 2) all0 &= (ebuf[j] == 0u);
        g_is64 = all0;
    }
}

// degree count, reading edge buffer directly
__global__ void k_count(const void* __restrict__ ebuf) {
    int e = blockIdx.x * blockDim.x + threadIdx.x;
    if (e >= N_EDGES) return;
    int d = g_is64 ? (int)((const long long*)ebuf)[N_EDGES + e]
                   : ((const int*)ebuf)[N_EDGES + e];
    atomicAdd(&g_cursor[d], 1);
}

// batch conversion + graph boundaries + per-node batch store
__global__ void k_gptr(const void* __restrict__ bbuf) {
    int i = blockIdx.x * blockDim.x + threadIdx.x;
    if (i >= N_NODES) return;
    int is64 = g_is64;
    int b = is64 ? (int)((const long long*)bbuf)[i] : ((const int*)bbuf)[i];
    g_batch[i] = b;
}

// ---------------- scans ----------------
__global__ void k_scan_a() {
    __shared__ int red[256];
    int b = blockIdx.x, t = threadIdx.x;
    int base = b * 1024 + t * 4;
    int s = 0;
#pragma unroll
    for (int j = 0; j < 4; j++) {
        int idx = base + j;
        if (idx < N_NODES) {
            int c = g_cursor[idx];
            s += c;
            g_dis[idx] = rsqrtf((float)c);
        }
    }
    red[t] = s; __syncthreads();
    for (int off = 128; off > 0; off >>= 1) {
        if (t < off) red[t] += red[t + off];
        __syncthreads();
    }
    if (t == 0) g_bsum[b] = red[0];
}

__global__ void k_scan_b() {
    int lane = threadIdx.x;
    int base = lane * 4;
    int c[4]; int s = 0;
#pragma unroll
    for (int j = 0; j < 4; j++) {
        c[j] = (base + j < NBLK_SCAN) ? g_bsum[base + j] : 0;
        s += c[j];
    }
    int x = s;
#pragma unroll
    for (int off = 1; off < 32; off <<= 1) {
        int y = __shfl_up_sync(0xffffffffu, x, off);
        if (lane >= off) x += y;
    }
    int acc = x - s;
#pragma unroll
    for (int j = 0; j < 4; j++) {
        if (base + j < NBLK_SCAN) g_boff[base + j] = acc;
        acc += c[j];
    }
    if (lane == 31) g_colptr[N_NODES] = x;
}

__global__ void k_scan_c() {
    __shared__ int wsum[8], woff[8];
    int b = blockIdx.x, t = threadIdx.x;
    int base = b * 1024 + t * 4;
    int v[4];
#pragma unroll
    for (int j = 0; j < 4; j++) {
        int idx = base + j;
        v[j] = (idx < N_NODES) ? g_cursor[idx] : 0;
    }
    int s = v[0] + v[1] + v[2] + v[3];
    int lane = t & 31, w = t >> 5;
    int x = s;
#pragma unroll
    for (int off = 1; off < 32; off <<= 1) {
        int y = __shfl_up_sync(0xffffffffu, x, off);
        if (lane >= off) x += y;
    }
    if (lane == 31) wsum[w] = x;
    __syncthreads();
    if (t == 0) { int a = 0; for (int i = 0; i < 8; i++) { woff[i] = a; a += wsum[i]; } }
    __syncthreads();
    int excl = (x - s) + woff[w] + g_boff[b];
#pragma unroll
    for (int j = 0; j < 4; j++) {
        int idx = base + j;
        if (idx < N_NODES) {
            g_colptr[idx] = excl;
            g_csrsrc[excl] = idx;      // self loop
            g_cursor[idx] = excl + 1;
        }
        excl += v[j];
    }
}

__global__ void k_filledges(const void* __restrict__ ebuf) {
    int e = blockIdx.x * blockDim.x + threadIdx.x;
    if (e >= N_EDGES) return;
    int s, d;
    if (g_is64) {
        const long long* p = (const long long*)ebuf;
        s = (int)p[e]; d = (int)p[N_EDGES + e];
    } else {
        const int* p = (const int*)ebuf;
        s = p[e]; d = p[N_EDGES + e];
    }
    int pos = atomicAdd(&g_cursor[d], 1);
    g_csrsrc[pos] = s;
}

// ---------------- fused prep: BN consts + all weight transposes -----------
__global__ void k_prep(const float* __restrict__ W0, const float* __restrict__ Ws,
                       const float* __restrict__ bias, const float* __restrict__ gamma,
                       const float* __restrict__ beta, const float* __restrict__ mean,
                       const float* __restrict__ var) {
    int i = blockIdx.x * blockDim.x + threadIdx.x;
    if (i < 4 * H) {
        float s = gamma[i] * rsqrtf(var[i] + BN_EPS);
        g_bnS[i] = s;
        g_bnT[i] = (bias[i] - mean[i]) * s + beta[i];
        return;
    }
    int i0 = i - 4 * H;
    if (i0 < 104 * 48) {                     // layer 0: [104][48] <- W0[33][100]
        int n = i0 / 48, k = i0 % 48;
        g_Wh[i0] = (n < H && k < K0) ? __float2half(W0[k * H + n]) : __float2half(0.f);
        return;
    }
    int i1 = i0 - 104 * 48;
    if (i1 < 3 * WSL) {                      // layers 1-3: [104][112] <- Ws[l][100][100]
        int l = i1 / WSL, r = i1 % WSL;
        int n = r / 112, k = r % 112;
        g_Wh[WSL * (l + 1) + r] = (n < H && k < H)
            ? __float2half(Ws[l * H * H + k * H + n]) : __float2half(0.f);
    }
}

// ---------------- layer-0 aggregate (fused prescale): x -> g_hx fp16 -------
// warp per node; lane L accumulates channel L (ch 32 on lane 0)
__global__ void k_agg0(const float* __restrict__ x) {
    int gwarp = (blockIdx.x * blockDim.x + threadIdx.x) >> 5;
    int lane = threadIdx.x & 31;
    if (gwarp >= N_NODES) return;
    int n = gwarp;
    int beg = g_colptr[n], end = g_colptr[n + 1];
    float a = 0.f, a32 = 0.f;
    for (int i = beg; i < end; i++) {
        int s = g_csrsrc[i];                 // broadcast
        float ds = g_dis[s];                 // broadcast
        a = fmaf(ds, x[s * K0 + lane], a);
        if (lane == 0) a32 = fmaf(ds, x[s * K0 + 32], a32);
    }
    float dn = g_dis[n];
    g_hx[n * K0P + lane] = __float2half(a * dn);
    if (lane == 0) g_hx[n * K0P + 32] = __float2half(a32 * dn);
    else if (lane < 4) g_hx[n * K0P + 32 + lane] = __float2half(0.f);
}

// ---------------- tensor-core GEMM v2: BM=128, 8 warps, dynamic smem -------
// MODE 0: A=g_hx [N,36] -> g_h fp16, epi = BN(layer0)+ReLU
// MODE 1: A=g_h  [N,100] -> g_Y fp16, epi = *dis[row]
template <int KPAD, int KA, int MODE>
__global__ void __launch_bounds__(256) k_mma(const __half* __restrict__ Wp) {
    constexpr int KS = KPAD + 8;
    constexpr int C2 = KA / 2;
    constexpr int P2 = (KPAD - KA) / 2;
    extern __shared__ __half smem[];
    __half* As = smem;                 // [128][KS]
    __half* Bs = smem + 128 * KS;      // [104][KS]
    int row0 = blockIdx.x * 128;
    int tid = threadIdx.x;

    const __half* Asrc = (MODE == 0) ? g_hx : g_h;
    const __half2 z2 = __float2half2_rn(0.f);
    for (int i = tid; i < 128 * C2; i += 256) {
        int r = i / C2, c2 = i % C2;
        int gr = row0 + r;
        __half2 v = (gr < N_NODES) ? ((const __half2*)Asrc)[gr * C2 + c2] : z2;
        *(__half2*)&As[r * KS + c2 * 2] = v;
    }
    for (int i = tid; i < 128 * P2; i += 256) {
        int r = i / P2, j = i % P2;
        *(__half2*)&As[r * KS + KA + j * 2] = z2;
    }
    for (int i = tid; i < 104 * (KPAD / 2); i += 256) {
        int nn = i / (KPAD / 2), c2 = i % (KPAD / 2);
        __half2 v = ((const __half2*)Wp)[i];
        *(__half2*)&Bs[nn * KS + c2 * 2] = v;
    }
    __syncthreads();

    int warp = tid >> 5, lane = tid & 31;
    int g = lane >> 2, t = lane & 3;
    int r0 = warp * 16;
    float acc[13][4];
#pragma unroll
    for (int j = 0; j < 13; j++)
#pragma unroll
        for (int c = 0; c < 4; c++) acc[j][c] = 0.f;

#pragma unroll
    for (int ks = 0; ks < KPAD / 16; ks++) {
        int kb = ks * 16 + t * 2;
        unsigned a0 = *(unsigned*)&As[(r0 + g) * KS + kb];
        unsigned a1 = *(unsigned*)&As[(r0 + g + 8) * KS + kb];
        unsigned a2 = *(unsigned*)&As[(r0 + g) * KS + kb + 8];
        unsigned a3 = *(unsigned*)&As[(r0 + g + 8) * KS + kb + 8];
#pragma unroll
        for (int j = 0; j < 13; j++) {
            int nr = j * 8 + g;
            unsigned b0 = *(unsigned*)&Bs[nr * KS + kb];
            unsigned b1 = *(unsigned*)&Bs[nr * KS + kb + 8];
            asm volatile(
                "mma.sync.aligned.m16n8k16.row.col.f32.f16.f16.f32 "
                "{%0,%1,%2,%3}, {%4,%5,%6,%7}, {%8,%9}, {%0,%1,%2,%3};"
                : "+f"(acc[j][0]), "+f"(acc[j][1]), "+f"(acc[j][2]), "+f"(acc[j][3])
                : "r"(a0), "r"(a1), "r"(a2), "r"(a3), "r"(b0), "r"(b1));
        }
    }

    int gr0 = row0 + r0 + g;
    int gr1 = gr0 + 8;
    if (MODE == 0) {
#pragma unroll
        for (int j = 0; j < 13; j++) {
            int c = j * 8 + t * 2;
            if (c >= H) continue;
            float Sx = g_bnS[c], Sy = g_bnS[c + 1];
            float Tx = g_bnT[c], Ty = g_bnT[c + 1];
            if (gr0 < N_NODES) {
                float ox = fmaxf(fmaf(acc[j][0], Sx, Tx), 0.f);
                float oy = fmaxf(fmaf(acc[j][1], Sy, Ty), 0.f);
                __half2 hv = __floats2half2_rn(ox, oy);
                *(__half2*)&g_h[gr0 * H + c] = hv;
            }
            if (gr1 < N_NODES) {
                float ox = fmaxf(fmaf(acc[j][2], Sx, Tx), 0.f);
                float oy = fmaxf(fmaf(acc[j][3], Sy, Ty), 0.f);
                __half2 hv = __floats2half2_rn(ox, oy);
                *(__half2*)&g_h[gr1 * H + c] = hv;
            }
        }
    } else {
        float d0 = (gr0 < N_NODES) ? g_dis[gr0] : 0.f;
        float d1 = (gr1 < N_NODES) ? g_dis[gr1] : 0.f;
#pragma unroll
        for (int j = 0; j < 13; j++) {
            int c = j * 8 + t * 2;
            if (c >= H) continue;
            if (gr0 < N_NODES) {
                __half2 hv = __floats2half2_rn(acc[j][0] * d0, acc[j][1] * d0);
                *(__half2*)&g_Y[gr0 * H + c] = hv;
            }
            if (gr1 < N_NODES) {
                __half2 hv = __floats2half2_rn(acc[j][2] * d1, acc[j][3] * d1);
                *(__half2*)&g_Y[gr1 * H + c] = hv;
            }
        }
    }
}

// ---------------- aggregation: g_Y(fp16) -> g_h(fp16)  [LAST: fused pool] --
template <int LAST>
__global__ void k_agg(int layer, int relu, const float* __restrict__ hW) {
    int gwarp = (blockIdx.x * blockDim.x + threadIdx.x) >> 5;
    int lane = threadIdx.x & 31;
    if (gwarp >= N_NODES) return;
    int n = gwarp;
    float ox = 0.f, oy = 0.f, oz = 0.f, ow = 0.f;
    if (lane < H4) {
        int beg = g_colptr[n], end = g_colptr[n + 1];
        const uint2* Y2 = (const uint2*)g_Y;
        float a0x=0.f,a0y=0.f,a0z=0.f,a0w=0.f;
        float a1x=0.f,a1y=0.f,a1z=0.f,a1w=0.f;
        float a2x=0.f,a2y=0.f,a2z=0.f,a2w=0.f;
        float a3x=0.f,a3y=0.f,a3z=0.f,a3w=0.f;
        int i = beg;
        for (; i + 3 < end; i += 4) {
            int s0 = g_csrsrc[i], s1 = g_csrsrc[i+1], s2 = g_csrsrc[i+2], s3 = g_csrsrc[i+3];
            uint2 u0 = Y2[s0 * H4 + lane];
            uint2 u1 = Y2[s1 * H4 + lane];
            uint2 u2 = Y2[s2 * H4 + lane];
            uint2 u3 = Y2[s3 * H4 + lane];
            float2 p;
            p = __half22float2(*(__half2*)&u0.x); a0x += p.x; a0y += p.y;
            p = __half22float2(*(__half2*)&u0.y); a0z += p.x; a0w += p.y;
            p = __half22float2(*(__half2*)&u1.x); a1x += p.x; a1y += p.y;
            p = __half22float2(*(__half2*)&u1.y); a1z += p.x; a1w += p.y;
            p = __half22float2(*(__half2*)&u2.x); a2x += p.x; a2y += p.y;
            p = __half22float2(*(__half2*)&u2.y); a2z += p.x; a2w += p.y;
            p = __half22float2(*(__half2*)&u3.x); a3x += p.x; a3y += p.y;
            p = __half22float2(*(__half2*)&u3.y); a3z += p.x; a3w += p.y;
        }
        for (; i < end; i++) {
            int s0 = g_csrsrc[i];
            uint2 u0 = Y2[s0 * H4 + lane];
            float2 p;
            p = __half22float2(*(__half2*)&u0.x); a0x += p.x; a0y += p.y;
            p = __half22float2(*(__half2*)&u0.y); a0z += p.x; a0w += p.y;
        }
        float ax = (a0x + a1x) + (a2x + a3x);
        float ay = (a0y + a1y) + (a2y + a3y);
        float az = (a0z + a1z) + (a2z + a3z);
        float aw = (a0w + a1w) + (a2w + a3w);
        float d = g_dis[n];
        int c = layer * H + lane * 4;
        float4 S = *(const float4*)&g_bnS[c];
        float4 T = *(const float4*)&g_bnT[c];
        ox = fmaf(ax * d, S.x, T.x);
        oy = fmaf(ay * d, S.y, T.y);
        oz = fmaf(az * d, S.z, T.z);
        ow = fmaf(aw * d, S.w, T.w);
        if (relu) {
            ox = fmaxf(ox, 0.f); oy = fmaxf(oy, 0.f);
            oz = fmaxf(oz, 0.f); ow = fmaxf(ow, 0.f);
        }
    }
    if (LAST == 0) {
        if (lane < H4) {
            __half2 h0 = __floats2half2_rn(ox, oy);
            __half2 h1 = __floats2half2_rn(oz, ow);
            uint2 u; u.x = *(unsigned*)&h0; u.y = *(unsigned*)&h1;
            *(uint2*)&g_h[n * H + lane * 4] = u;
        }
    } else {
        float s = 0.f;
        if (lane < H4) {
            float4 w4 = ((const float4*)hW)[lane];
            s = ox * w4.x + oy * w4.y + oz * w4.z + ow * w4.w;
        }
#pragma unroll
        for (int off = 16; off > 0; off >>= 1)
            s += __shfl_down_sync(0xffffffffu, s, off);
        if (lane == 0) atomicAdd(&g_gsum[g_batch[n]], s);
    }
}

// ---------------- finish: bias + LeakyReLU ----------------
__global__ void k_finish(const float* __restrict__ hb, float* __restrict__ out) {
    int g = blockIdx.x * blockDim.x + threadIdx.x;
    if (g >= N_GRAPHSX) return;
    float o = g_gsum[g] + hb[0];
    out[g] = (o >= 0.f) ? o : 0.1f * o;
}

// ---------------- launch ----------------
extern "C" void kernel_launch(void* const* d_in, const int* in_sizes, int n_in,
                              void* d_out, int out_size) {
    const float* x      = (const float*)d_in[0];
    const void*  ei     = d_in[1];
    const void*  batch  = d_in[2];
    const float* W0     = (const float*)d_in[3];
    const float* Ws     = (const float*)d_in[4];
    const float* biases = (const float*)d_in[5];
    const float* gamma  = (const float*)d_in[6];
    const float* beta   = (const float*)d_in[7];
    const float* mean   = (const float*)d_in[8];
    const float* var    = (const float*)d_in[9];
    const float* headW  = (const float*)d_in[10];
    const float* headb  = (const float*)d_in[11];
    float* out = (float*)d_out;

    static int attr_done = 0;
    const int smem_big   = (128 + 104) * (112 + 8) * 2;  // 55680
    const int smem_small = (128 + 104) * (48 + 8) * 2;   // 25984
    if (!attr_done) {
        cudaFuncSetAttribute(k_mma<112, 100, 1>, cudaFuncAttributeMaxDynamicSharedMemorySize, smem_big);
        cudaFuncSetAttribute(k_mma<48, 36, 0>,   cudaFuncAttributeMaxDynamicSharedMemorySize, smem_small);
        attr_done = 1;
    }

    // device pointer to weight staging (device-global address, host-computable)
    __half* whp = nullptr;
    cudaGetSymbolAddress((void**)&whp, g_Wh);

    k_init<<<(N_NODES + 255) / 256, 256>>>((const unsigned*)ei);
    k_count<<<(N_EDGES + 255) / 256, 256>>>(ei);
    k_gptr<<<(N_NODES + 255) / 256, 256>>>(batch);
    k_scan_a<<<NBLK_SCAN, 256>>>();
    k_scan_b<<<1, 32>>>();
    k_scan_c<<<NBLK_SCAN, 256>>>();
    k_filledges<<<(N_EDGES + 255) / 256, 256>>>(ei);
    k_prep<<<(4 * H + 104 * 48 + 3 * WSL + 255) / 256, 256>>>(W0, Ws, biases, gamma, beta, mean, var);

    int mma_blocks = (N_NODES + 127) / 128;
    int agg_blocks = (N_NODES * 32 + 255) / 256;

    // layer 0: fused prescale+aggregate -> MMA (BN0+ReLU)
    k_agg0<<<agg_blocks, 256>>>(x);
    k_mma<48, 36, 0><<<mma_blocks, 256, smem_small>>>(whp);
    // layers 1..3
    for (int l = 1; l < 4; l++) {
        k_mma<112, 100, 1><<<mma_blocks, 256, smem_big>>>(whp + l * WSL);
        if (l < 3) k_agg<0><<<agg_blocks, 256>>>(l, 1, headW);
        else       k_agg<1><<<agg_blocks, 256>>>(l, 0, headW);
    }

    k_finish<<<(N_GRAPHSX + 255) / 256, 256>>>(headb, out);
}